// round 14
// baseline (speedup 1.0000x reference)
#include <cuda_runtime.h>
#include <math.h>

#define Bb   8
#define Ss   4096
#define Dd   32
#define Nst  16
#define HIDn 128
#define Ll   64
#define CPB  64
#define NCHUNK 512
#define NGRP 8
#define GL   8
#define TOK  32768
#define XPAD 36
#define YSZ  ((size_t)TOK*Dd)
#define OUT_ELEMS ((size_t)TOK*Dd*Dd)

// ---------------- scratch ----------------------------------------------------
__device__ float g_P    [NCHUNK*Nst];
__device__ float g_sL   [NCHUNK*512];
__device__ float g_yloc4[4*TOK*Dd];   // 4 n-quarter partials of y_local
__device__ float g_cpi  [TOK*Nst];
__device__ float g_hinL [NCHUNK*512];
__device__ float g_Hg   [Bb*NGRP*512];
__device__ float g_Plp  [Bb*NGRP*GL*Nst];
__device__ float g_SxP  [NCHUNK*Dd];
__device__ float g_SxxP [NCHUNK];
__device__ float g_lossB[Bb];
// fused weights (k0 outputs)
__device__ float g_fWB  [Dd*Nst];     // Win @ WB
__device__ float g_fWC  [Dd*Nst];     // Win @ WC
__device__ float g_fbB  [Nst];        // bin @ WB
__device__ float g_fbC  [Nst];        // bin @ WC
__device__ float g_fweff[Dd];         // Win @ (Wdt@Wdtr)
__device__ float g_fc0;               // bin.(Wdt@Wdtr) + bdt.Wdtr

// ---------------- K0: fuse weight products ----------------------------------
__global__ __launch_bounds__(512) void k0_fuse(
    const float* __restrict__ Win, const float* __restrict__ binp,
    const float* __restrict__ Wdt, const float* __restrict__ bdt,
    const float* __restrict__ Wdtr,
    const float* __restrict__ WB,  const float* __restrict__ WC)
{
    __shared__ float sweff[Dd];
    int tid = threadIdx.x;
    if (tid < Dd) {
        float s = 0.f;
        #pragma unroll
        for (int r = 0; r < Nst; r++) s += Wdt[tid*Nst + r] * Wdtr[r];
        sweff[tid] = s;
    }
    __syncthreads();

    {   // fused Win@WB, Win@WC (one element per thread)
        int k = tid >> 4, n = tid & 15;
        float fb = 0.f, fc = 0.f;
        #pragma unroll
        for (int j = 0; j < Dd; j++) {
            float w = Win[k*Dd + j];
            fb = fmaf(w, WB[j*Nst + n], fb);
            fc = fmaf(w, WC[j*Nst + n], fc);
        }
        g_fWB[k*Nst + n] = fb;
        g_fWC[k*Nst + n] = fc;
    }
    if (tid < Dd) {
        float s = 0.f;
        #pragma unroll
        for (int j = 0; j < Dd; j++) s += Win[tid*Dd + j] * sweff[j];
        g_fweff[tid] = s;
    }
    if (tid >= 64 && tid < 64 + Nst) {
        int n = tid - 64;
        float sb = 0.f, sc = 0.f;
        #pragma unroll
        for (int j = 0; j < Dd; j++) {
            sb = fmaf(binp[j], WB[j*Nst + n], sb);
            sc = fmaf(binp[j], WC[j*Nst + n], sc);
        }
        g_fbB[n] = sb; g_fbC[n] = sc;
    }
    if (tid == 96) {
        float s = 0.f;
        #pragma unroll
        for (int j = 0; j < Dd; j++) s += binp[j] * sweff[j];
        #pragma unroll
        for (int r = 0; r < Nst; r++) s += bdt[r] * Wdtr[r];
        g_fc0 = s;
    }
}

// ---------------- KP: fused projection + 4-warp scan (block=256=1 chunk) ----
__global__ __launch_bounds__(256) void kP(
    const float* __restrict__ x, const float* __restrict__ A,
    const float* __restrict__ Win, const float* __restrict__ binp)
{
    __shared__ __align__(16) float4 sWin4[Dd*8];     // 4 KB
    __shared__ __align__(16) float4 sFB4[Dd*4], sFC4[Dd*4];  // 2+2 KB
    __shared__ __align__(16) float4 sbin4[8], sbB4[4], sbC4[4], sweff4[8];
    __shared__ __align__(16) float4 sa4 [Ll*4];      // a   4 KB
    __shared__ __align__(16) float4 sbd4[Ll*4];      // bd  4 KB
    __shared__ __align__(16) float4 sc4 [Ll*4];      // c   4 KB
    __shared__ __align__(16) float  sxp [Ll*XPAD];   // 9 KB
    __shared__ float sA[Nst], szz[Ll];
    __shared__ float sSx4[4][Dd], sSxx4[4];
    __shared__ float sc0;

    int tid = threadIdx.x;
    int ch  = blockIdx.x;

    for (int i = tid; i < Dd*8; i += 256) sWin4[i] = ((const float4*)Win)[i];
    for (int i = tid; i < Dd*4; i += 256) { sFB4[i] = ((const float4*)g_fWB)[i];
                                            sFC4[i] = ((const float4*)g_fWC)[i]; }
    if (tid < 8)       sbin4[tid]  = ((const float4*)binp)[tid];
    else if (tid < 12) sbB4[tid-8] = ((const float4*)g_fbB)[tid-8];
    else if (tid < 16) sbC4[tid-12]= ((const float4*)g_fbC)[tid-12];
    else if (tid < 24) sweff4[tid-16] = ((const float4*)g_fweff)[tid-16];
    else if (tid < 40) sA[tid-24] = A[tid-24];
    else if (tid == 40) sc0 = g_fc0;
    __syncthreads();

    int tl = tid & 63;          // token in chunk
    int q  = tid >> 6;          // 0..3, warp-uniform role

    // ---- phase A1: xp-slice + (B|C)-slice directly from x ----
    float pacc[8];              // projection slice (B or C), kept for A2
    {
        float xr[32];
        const float4* xg = (const float4*)x + ((size_t)ch*Ll + tl)*8;
        #pragma unroll
        for (int j = 0; j < 8; j++) {
            float4 v = xg[j];
            xr[j*4+0] = v.x; xr[j*4+1] = v.y; xr[j*4+2] = v.z; xr[j*4+3] = v.w;
        }

        // xp slice [8q, 8q+8)
        float xa[8];
        {
            float4 b0 = sbin4[2*q], b1 = sbin4[2*q+1];
            xa[0]=b0.x; xa[1]=b0.y; xa[2]=b0.z; xa[3]=b0.w;
            xa[4]=b1.x; xa[5]=b1.y; xa[6]=b1.z; xa[7]=b1.w;
        }
        // B/C slice: q0:B[0:8) q1:B[8:16) q2:C[0:8) q3:C[8:16)
        {
            int half = q & 1;
            float4 b0 = (q < 2) ? sbB4[2*half] : sbC4[2*half];
            float4 b1 = (q < 2) ? sbB4[2*half+1] : sbC4[2*half+1];
            pacc[0]=b0.x; pacc[1]=b0.y; pacc[2]=b0.z; pacc[3]=b0.w;
            pacc[4]=b1.x; pacc[5]=b1.y; pacc[6]=b1.z; pacc[7]=b1.w;
        }
        const float4* Wf = (q < 2) ? sFB4 : sFC4;
        int fc0i = 2*(q & 1);

        #pragma unroll
        for (int k = 0; k < 32; k++) {
            float xk = xr[k];
            float4 w0 = sWin4[k*8 + 2*q], w1 = sWin4[k*8 + 2*q + 1];
            xa[0]=fmaf(xk,w0.x,xa[0]); xa[1]=fmaf(xk,w0.y,xa[1]);
            xa[2]=fmaf(xk,w0.z,xa[2]); xa[3]=fmaf(xk,w0.w,xa[3]);
            xa[4]=fmaf(xk,w1.x,xa[4]); xa[5]=fmaf(xk,w1.y,xa[5]);
            xa[6]=fmaf(xk,w1.z,xa[6]); xa[7]=fmaf(xk,w1.w,xa[7]);
            float4 f0 = Wf[k*4 + fc0i], f1 = Wf[k*4 + fc0i + 1];
            pacc[0]=fmaf(xk,f0.x,pacc[0]); pacc[1]=fmaf(xk,f0.y,pacc[1]);
            pacc[2]=fmaf(xk,f0.z,pacc[2]); pacc[3]=fmaf(xk,f0.w,pacc[3]);
            pacc[4]=fmaf(xk,f1.x,pacc[4]); pacc[5]=fmaf(xk,f1.y,pacc[5]);
            pacc[6]=fmaf(xk,f1.z,pacc[6]); pacc[7]=fmaf(xk,f1.w,pacc[7]);
        }

        float4* xrow = (float4*)&sxp[tl*XPAD];
        xrow[2*q]   = make_float4(xa[0], xa[1], xa[2], xa[3]);
        xrow[2*q+1] = make_float4(xa[4], xa[5], xa[6], xa[7]);

        if (q == 0) {     // dt pre-activation
            float zp = 0.f;
            #pragma unroll
            for (int j = 0; j < 8; j++) {
                float4 wv = sweff4[j];
                zp = fmaf(xr[j*4+0], wv.x, zp);
                zp = fmaf(xr[j*4+1], wv.y, zp);
                zp = fmaf(xr[j*4+2], wv.z, zp);
                zp = fmaf(xr[j*4+3], wv.w, zp);
            }
            szz[tl] = zp;
        }
    }
    __syncthreads();

    // ---- phase A2: dt; stage a / bd / c ----
    {
        float zs = szz[tl] + sc0;
        float dtv = fmaxf(zs, 0.f) + log1pf(expf(-fabsf(zs)));
        // a: q writes n [4q, 4q+4)
        sa4[tl*4 + q] = make_float4(expf(dtv*sA[4*q+0]), expf(dtv*sA[4*q+1]),
                                    expf(dtv*sA[4*q+2]), expf(dtv*sA[4*q+3]));
        if (q < 2) {      // bd = dt * B-slice
            sbd4[tl*4 + 2*q+0] = make_float4(dtv*pacc[0], dtv*pacc[1], dtv*pacc[2], dtv*pacc[3]);
            sbd4[tl*4 + 2*q+1] = make_float4(dtv*pacc[4], dtv*pacc[5], dtv*pacc[6], dtv*pacc[7]);
        } else {          // c
            int hh = q & 1;
            sc4[tl*4 + 2*hh+0] = make_float4(pacc[0], pacc[1], pacc[2], pacc[3]);
            sc4[tl*4 + 2*hh+1] = make_float4(pacc[4], pacc[5], pacc[6], pacc[7]);
        }
    }
    __syncthreads();

    int warp = tid >> 5, lane = tid & 31;

    if (warp < 4) {
        // ---- scan: warp owns n [4w, 4w+4); lane = d ----
        float h0=0.f, h1=0.f, h2=0.f, h3=0.f;
        float* yw = g_yloc4 + (size_t)warp*YSZ + (size_t)ch*Ll*Dd + lane;

        #pragma unroll 2
        for (int t = 0; t < Ll; t++) {
            float4 av = sa4 [t*4 + warp];
            float4 bv = sbd4[t*4 + warp];
            float4 cv = sc4 [t*4 + warp];
            float xv = sxp[t*XPAD + lane];
            h0 = fmaf(av.x, h0, bv.x*xv);
            h1 = fmaf(av.y, h1, bv.y*xv);
            h2 = fmaf(av.z, h2, bv.z*xv);
            h3 = fmaf(av.w, h3, bv.w*xv);
            float y0 = cv.x*h0;  y0 = fmaf(cv.y, h1, y0);
            float y1 = cv.z*h2;  y1 = fmaf(cv.w, h3, y1);
            yw[t*Dd] = y0 + y1;
        }
        // sL: off = d*16 + n
        *(float4*)(g_sL + (size_t)ch*512 + lane*16 + 4*warp) = make_float4(h0,h1,h2,h3);
    } else {
        int w2 = warp - 4;
        // ---- stats: tokens [16*w2, 16*w2+16) ----
        {
            const float* xb = x + ((size_t)ch*Ll + w2*16)*Dd;
            float s = 0.f, sq = 0.f;
            #pragma unroll
            for (int t = 0; t < 16; t++) {
                float v = xb[t*Dd + lane];
                s += v; sq = fmaf(v, v, sq);
            }
            sSx4[w2][lane] = s;
            #pragma unroll
            for (int m = 16; m >= 1; m >>= 1) sq += __shfl_xor_sync(0xffffffffu, sq, m);
            if (lane == 0) sSxx4[w2] = sq;
        }
        // ---- cpi/P chains: n = 4*w2 + lane (lanes 0-3) ----
        if (lane < 4) {
            int n = 4*w2 + lane;
            const float* saf = (const float*)sa4;
            const float* scf = (const float*)sc4;
            float* cpio = g_cpi + (size_t)ch*Ll*Nst;
            float pis = 1.f;
            #pragma unroll 4
            for (int t = 0; t < Ll; t++) {
                pis *= saf[t*16 + n];
                cpio[t*Nst + n] = scf[t*16 + n] * pis;
            }
            g_P[ch*Nst + n] = pis;
        }
    }
    __syncthreads();

    if (tid < Dd)  g_SxP[ch*Dd + tid] = (sSx4[0][tid] + sSx4[1][tid])
                                      + (sSx4[2][tid] + sSx4[3][tid]);
    if (tid == 32) g_SxxP[ch] = (sSxx4[0] + sSxx4[1]) + (sSxx4[2] + sSxx4[3]);
}

// ---------------- K3: per-batch combine + stat reduce + MLP loss ------------
__global__ __launch_bounds__(512) void k3(
    const float* __restrict__ Wd1, const float* __restrict__ bd1,
    const float* __restrict__ Wd2, const float* __restrict__ bd2,
    const float* __restrict__ Wd3, const float* __restrict__ bd3)
{
    __shared__ float sgend[NGRP*512];
    __shared__ float sPg[NGRP*Nst];
    __shared__ float sh[512];
    __shared__ float hrep[Nst], z1[HIDn], z2[HIDn], uu[Dd];
    __shared__ float sSxb[Dd], sSxxb;

    int b = blockIdx.x, off = threadIdx.x, n = off & 15;

    #pragma unroll
    for (int g = 0; g < NGRP; g++) {
        float lp[GL], ls[GL];
        #pragma unroll
        for (int j = 0; j < GL; j++) {
            int c = b*CPB + g*GL + j;
            lp[j] = g_P [c*Nst + n];
            ls[j] = g_sL[(size_t)c*512 + off];
        }
        float h = 0.f, pl = 1.f;
        #pragma unroll
        for (int j = 0; j < GL; j++) {
            int c = b*CPB + g*GL + j;
            g_hinL[(size_t)c*512 + off] = h;
            if (off < 16) g_Plp[((b*NGRP+g)*GL + j)*Nst + off] = pl;
            h  = fmaf(lp[j], h, ls[j]);
            pl *= lp[j];
        }
        sgend[g*512 + off] = h;
        if (off < 16) sPg[g*Nst + off] = pl;
    }
    __syncthreads();

    {
        float pg[NGRP], ge[NGRP];
        #pragma unroll
        for (int g = 0; g < NGRP; g++) {
            pg[g] = sPg[g*Nst + n];
            ge[g] = sgend[g*512 + off];
        }
        float h = 0.f;
        #pragma unroll
        for (int g = 0; g < NGRP; g++) {
            g_Hg[(size_t)(b*NGRP+g)*512 + off] = h;
            h = fmaf(pg[g], h, ge[g]);
        }
        sh[off] = h;
    }

    if (off < Dd) {
        float s = 0.f;
        #pragma unroll 8
        for (int k = 0; k < CPB; k++) s += g_SxP[(b*CPB + k)*Dd + off];
        sSxb[off] = s;
    } else if (off >= 32 && off < 64) {
        int l = off - 32;
        float s = g_SxxP[b*CPB + l] + g_SxxP[b*CPB + 32 + l];
        #pragma unroll
        for (int m = 16; m >= 1; m >>= 1) s += __shfl_xor_sync(0xffffffffu, s, m);
        if (l == 0) sSxxb = s;
    }
    __syncthreads();

    if (off < Nst) {
        float s = 0.f;
        #pragma unroll
        for (int d = 0; d < Dd; d++) s += sh[d*Nst + off];
        hrep[off] = s * (1.f/(float)Dd);
    }
    __syncthreads();
    if (off < HIDn) {
        float acc = bd1[off];
        #pragma unroll
        for (int nn = 0; nn < Nst; nn++) acc += hrep[nn] * Wd1[nn*HIDn + off];
        z1[off] = fmaxf(acc, 0.f);
    }
    __syncthreads();
    if (off < HIDn) {
        float acc = bd2[off];
        #pragma unroll 8
        for (int j = 0; j < HIDn; j++) acc += z1[j] * Wd2[j*HIDn + off];
        z2[off] = fmaxf(acc, 0.f);
    }
    __syncthreads();
    if (off < Dd) {
        float acc = bd3[off];
        #pragma unroll 8
        for (int j = 0; j < HIDn; j++) acc += z2[j] * Wd3[j*Dd + off];
        uu[off] = acc;
    }
    __syncthreads();
    if (off == 0) {
        float t1 = 0.f, t2 = 0.f;
        #pragma unroll
        for (int d = 0; d < Dd; d++) {
            t1 += uu[d]*uu[d];
            t2 += uu[d]*sSxb[d];
        }
        g_lossB[b] = (float)Ss * t1 - 2.f*t2 + sSxxb;
    }
}

// ---------------- K4: block-per-chunk y recombine + streaming expansion -----
__global__ __launch_bounds__(512) void k4(
    const float* __restrict__ Wout, const float* __restrict__ bout,
    float* __restrict__ out, long long out_size)
{
    __shared__ float shin[Dd*17];
    __shared__ float scpi[Ll*Nst];
    __shared__ float sy[Ll*Dd];
    __shared__ float4 sw[8], sb[8];

    int tid = threadIdx.x, ch = blockIdx.x;
    int bg = ch >> 3, j = ch & 7;

    {
        int d = tid >> 4, n = tid & 15;
        shin[d*17 + n] = fmaf(g_Plp[(bg*GL + j)*Nst + n],
                              g_Hg[(size_t)bg*512 + tid],
                              g_hinL[(size_t)ch*512 + tid]);
    }
    scpi[tid]       = g_cpi[(size_t)ch*1024 + tid];
    scpi[tid + 512] = g_cpi[(size_t)ch*1024 + 512 + tid];
    if (tid < 8)       sw[tid]   = ((const float4*)Wout)[tid];
    else if (tid < 16) sb[tid-8] = ((const float4*)bout)[tid-8];
    __syncthreads();

    size_t base = (size_t)ch*2048;
    #pragma unroll
    for (int k = 0; k < 4; k++) {
        int idx = tid + k*512;
        int t = idx >> 5, d = idx & 31;
        float y = (g_yloc4[base + idx] + g_yloc4[YSZ + base + idx])
                + (g_yloc4[2*YSZ + base + idx] + g_yloc4[3*YSZ + base + idx]);
        #pragma unroll
        for (int n = 0; n < Nst; n++)
            y = fmaf(scpi[t*Nst + n], shin[d*17 + n], y);
        sy[idx] = y;
    }
    __syncthreads();

    {
        int q = tid & 7, r0 = tid >> 3;
        float4 w4 = sw[q], b4 = sb[q];
        float4* o = (float4*)out + (size_t)ch*16384;
        #pragma unroll
        for (int k = 0; k < 32; k++) {
            int r = r0 + k*64;
            float y = sy[r];
            float4 v;
            v.x = fmaf(y, w4.x, b4.x);
            v.y = fmaf(y, w4.y, b4.y);
            v.z = fmaf(y, w4.z, b4.z);
            v.w = fmaf(y, w4.w, b4.w);
            __stcs(&o[r*8 + q], v);
        }
    }

    if (ch == 0 && tid == 0 && out_size > (long long)OUT_ELEMS) {
        float s = 0.f;
        #pragma unroll
        for (int b = 0; b < Bb; b++) s += g_lossB[b];
        out[out_size - 1] = s * (1.f/(float)(Bb*Ss));
    }
}

// ---------------- launch -----------------------------------------------------
extern "C" void kernel_launch(void* const* d_in, const int* in_sizes, int n_in,
                              void* d_out, int out_size)
{
    const float* x    = (const float*)d_in[0];
    const float* A    = (const float*)d_in[1];
    const float* Win  = (const float*)d_in[2];
    const float* binp = (const float*)d_in[3];
    const float* Wdt  = (const float*)d_in[4];
    const float* bdt  = (const float*)d_in[5];
    const float* Wdtr = (const float*)d_in[6];
    const float* WB   = (const float*)d_in[7];
    const float* WC   = (const float*)d_in[8];
    const float* Wout = (const float*)d_in[9];
    const float* bout = (const float*)d_in[10];
    const float* Wd1  = (const float*)d_in[11];
    const float* bd1  = (const float*)d_in[12];
    const float* Wd2  = (const float*)d_in[13];
    const float* bd2  = (const float*)d_in[14];
    const float* Wd3  = (const float*)d_in[15];
    const float* bd3  = (const float*)d_in[16];
    float* out = (float*)d_out;

    k0_fuse<<<1, 512>>>(Win, binp, Wdt, bdt, Wdtr, WB, WC);
    kP     <<<NCHUNK, 256>>>(x, A, Win, binp);
    k3     <<<Bb, 512>>>(Wd1, bd1, Wd2, bd2, Wd3, bd3);
    k4     <<<NCHUNK, 512>>>(Wout, bout, out, (long long)out_size);
}

// round 15
// speedup vs baseline: 1.1453x; 1.1453x over previous
#include <cuda_runtime.h>
#include <math.h>

#define Bb   8
#define Ss   4096
#define Dd   32
#define Nst  16
#define HIDn 128
#define Ll   64
#define CPB  64
#define NCHUNK 512
#define NGRP 8
#define GL   8
#define TOK  32768
#define XPAD 36                       // padded xp row stride (floats)
#define OUT_ELEMS ((size_t)TOK*Dd*Dd)

// ---------------- scratch ----------------------------------------------------
__device__ float g_P    [NCHUNK*Nst];
__device__ float g_sL   [NCHUNK*512];
__device__ float g_ylocA[TOK*Dd];     // y partial, n in [0,8)
__device__ float g_ylocB[TOK*Dd];     // y partial, n in [8,16)
__device__ float g_cpi  [TOK*Nst];
__device__ float g_hinL [NCHUNK*512];
__device__ float g_Hg   [Bb*NGRP*512];
__device__ float g_Plp  [Bb*NGRP*GL*Nst];
__device__ float g_SxP  [NCHUNK*Dd];
__device__ float g_SxxP [NCHUNK];
__device__ float g_lossB[Bb];

// ---------------- KP: fused projection + 2-warp split scan (R11 best) -------
// block = 64 threads = one chunk; grid = 512.
__global__ __launch_bounds__(64) void kP(
    const float* __restrict__ x,   const float* __restrict__ A,
    const float* __restrict__ Win, const float* __restrict__ binp,
    const float* __restrict__ Wdt, const float* __restrict__ bdt,
    const float* __restrict__ Wdtr,
    const float* __restrict__ WB,  const float* __restrict__ WC)
{
    // staging (float4): [a 256 | bd 256 | c 256 | x 512]
    __shared__ __align__(16) float4 sstage[1280];        // 20 KB
    __shared__ __align__(16) float4 sWin4[Dd*8];         // 4 KB
    __shared__ __align__(16) float4 sWB4[Dd*4], sWC4[Dd*4];
    __shared__ __align__(16) float4 sbin4[8];
    __shared__ __align__(16) float syP[2*2048];          // 16 KB partial y
    __shared__ float sweff[Dd], sA[Nst];
    __shared__ float sSx2[2][Dd];
    __shared__ float sSxx2[2];
    __shared__ float sc0;

    int tid = threadIdx.x;
    int ch  = blockIdx.x;
    int token = ch*Ll + tid;

    for (int i = tid; i < Dd*8; i += 64) sWin4[i] = ((const float4*)Win)[i];
    for (int i = tid; i < Dd*4; i += 64) { sWB4[i] = ((const float4*)WB)[i];
                                           sWC4[i] = ((const float4*)WC)[i]; }
    if (tid < 8) sbin4[tid] = ((const float4*)binp)[tid];
    if (tid < Dd) {
        float s = 0.f;
        #pragma unroll
        for (int r = 0; r < Nst; r++) s += Wdt[tid*Nst + r] * Wdtr[r];
        sweff[tid] = s;
    }
    if (tid == 32) {
        float s = 0.f;
        #pragma unroll
        for (int r = 0; r < Nst; r++) s += bdt[r] * Wdtr[r];
        sc0 = s;
    }
    if (tid >= 40 && tid < 40 + Nst) sA[tid-40] = A[tid-40];
    __syncthreads();

    // ---- phase A: projection, one token per thread ----
    float xr[32];
    {
        const float4* xg = (const float4*)x + (size_t)token*8;
        #pragma unroll
        for (int j = 0; j < 8; j++) {
            float4 v = xg[j];
            xr[j*4+0] = v.x; xr[j*4+1] = v.y; xr[j*4+2] = v.z; xr[j*4+3] = v.w;
        }
    }

    float xp[32];
    #pragma unroll
    for (int j = 0; j < 8; j++) {
        float4 b = sbin4[j];
        xp[j*4+0] = b.x; xp[j*4+1] = b.y; xp[j*4+2] = b.z; xp[j*4+3] = b.w;
    }
    #pragma unroll
    for (int k = 0; k < 32; k++) {
        float xk = xr[k];
        #pragma unroll
        for (int j = 0; j < 8; j++) {
            float4 w = sWin4[k*8+j];
            xp[j*4+0] = fmaf(xk, w.x, xp[j*4+0]);
            xp[j*4+1] = fmaf(xk, w.y, xp[j*4+1]);
            xp[j*4+2] = fmaf(xk, w.z, xp[j*4+2]);
            xp[j*4+3] = fmaf(xk, w.w, xp[j*4+3]);
        }
    }

    float zz = sc0;
    #pragma unroll
    for (int k = 0; k < 32; k++) zz = fmaf(xp[k], sweff[k], zz);
    float dt = fmaxf(zz, 0.f) + log1pf(expf(-fabsf(zz)));

    float bb[16], cc[16];
    #pragma unroll
    for (int n = 0; n < 16; n++) { bb[n] = 0.f; cc[n] = 0.f; }
    #pragma unroll
    for (int k = 0; k < 32; k++) {
        float xpk = xp[k];
        #pragma unroll
        for (int j = 0; j < 4; j++) {
            float4 wb = sWB4[k*4+j], wc = sWC4[k*4+j];
            bb[j*4+0] = fmaf(xpk, wb.x, bb[j*4+0]);
            bb[j*4+1] = fmaf(xpk, wb.y, bb[j*4+1]);
            bb[j*4+2] = fmaf(xpk, wb.z, bb[j*4+2]);
            bb[j*4+3] = fmaf(xpk, wb.w, bb[j*4+3]);
            cc[j*4+0] = fmaf(xpk, wc.x, cc[j*4+0]);
            cc[j*4+1] = fmaf(xpk, wc.y, cc[j*4+1]);
            cc[j*4+2] = fmaf(xpk, wc.z, cc[j*4+2]);
            cc[j*4+3] = fmaf(xpk, wc.w, cc[j*4+3]);
        }
    }

    #pragma unroll
    for (int j = 0; j < 4; j++) {
        sstage[      tid*4 + j] = make_float4(expf(dt*sA[j*4+0]), expf(dt*sA[j*4+1]),
                                              expf(dt*sA[j*4+2]), expf(dt*sA[j*4+3]));
        sstage[256 + tid*4 + j] = make_float4(dt*bb[j*4+0], dt*bb[j*4+1],
                                              dt*bb[j*4+2], dt*bb[j*4+3]);
        sstage[512 + tid*4 + j] = make_float4(cc[j*4+0], cc[j*4+1], cc[j*4+2], cc[j*4+3]);
    }
    #pragma unroll
    for (int j = 0; j < 8; j++)
        sstage[768 + tid*8 + j] = make_float4(xp[j*4+0], xp[j*4+1], xp[j*4+2], xp[j*4+3]);

    int warp = tid >> 5, lane = tid & 31;

    // ---- phase A2: x-stats, t-range split across warps ----
    {
        const float* xb = x + (size_t)ch*Ll*Dd + (size_t)warp*32*Dd;
        float s = 0.f, sq = 0.f;
        #pragma unroll 8
        for (int t = 0; t < 32; t++) {
            float v = xb[t*Dd + lane];
            s += v; sq = fmaf(v, v, sq);
        }
        sSx2[warp][lane] = s;
        #pragma unroll
        for (int m = 16; m >= 1; m >>= 1) sq += __shfl_xor_sync(0xffffffffu, sq, m);
        if (lane == 0) sSxx2[warp] = sq;
    }
    __syncthreads();

    // ---- phase B: scan; warp owns n in [8*warp, 8*warp+8) ----
    {
        const float4* s  = sstage;
        const float*  sa = (const float*)s;
        const float*  sc = (const float*)(s + 512);
        const float*  sx = (const float*)(s + 768);
        int np = warp*8 + (lane & 7);

        float h[8];
        #pragma unroll
        for (int n = 0; n < 8; n++) h[n] = 0.f;
        float pis = 1.f;

        float* syw  = syP + warp*2048;
        float* cpio = g_cpi + (size_t)ch*Ll*Nst;

        #pragma unroll 2
        for (int t = 0; t < Ll; t++) {
            float av[8], bv[8], cv[8];
            *(float4*)&av[0] = s[t*4 + warp*2 + 0];       *(float4*)&av[4] = s[t*4 + warp*2 + 1];
            *(float4*)&bv[0] = s[256 + t*4 + warp*2 + 0]; *(float4*)&bv[4] = s[256 + t*4 + warp*2 + 1];
            *(float4*)&cv[0] = s[512 + t*4 + warp*2 + 0]; *(float4*)&cv[4] = s[512 + t*4 + warp*2 + 1];
            float xv = sx[t*32 + lane];

            float y0 = 0.f, y1 = 0.f;
            #pragma unroll
            for (int n = 0; n < 8; n += 2) {
                h[n+0] = fmaf(av[n+0], h[n+0], bv[n+0]*xv); y0 = fmaf(cv[n+0], h[n+0], y0);
                h[n+1] = fmaf(av[n+1], h[n+1], bv[n+1]*xv); y1 = fmaf(cv[n+1], h[n+1], y1);
            }
            syw[t*32 + lane] = y0 + y1;

            pis *= sa[t*16 + np];
            if (lane < 8) cpio[t*Nst + np] = sc[t*16 + np] * pis;
        }

        float4* outL = (float4*)g_sL + (size_t)ch*128 + lane*4 + warp*2;
        outL[0] = make_float4(h[0],h[1],h[2],h[3]);
        outL[1] = make_float4(h[4],h[5],h[6],h[7]);
        if (lane < 8) g_P[ch*Nst + np] = pis;
    }
    __syncthreads();

    // ---- combine y halves + stats, write out ----
    {
        const float4* p0 = (const float4*)syP;
        const float4* p1 = (const float4*)(syP + 2048);
        float4* yo = (float4*)g_ylocA + (size_t)ch*512;
        #pragma unroll
        for (int k = 0; k < 8; k++) {
            int idx = tid + k*64;
            float4 a = p0[idx], b = p1[idx];
            yo[idx] = make_float4(a.x+b.x, a.y+b.y, a.z+b.z, a.w+b.w);
        }
    }
    if (tid < Dd)  g_SxP[ch*Dd + tid] = sSx2[0][tid] + sSx2[1][tid];
    if (tid == 32) g_SxxP[ch] = sSxx2[0] + sSxx2[1];
}

// ---------------- K3: per-batch combine + stat reduce + MLP loss ------------
__global__ __launch_bounds__(512) void k3(
    const float* __restrict__ Wd1, const float* __restrict__ bd1,
    const float* __restrict__ Wd2, const float* __restrict__ bd2,
    const float* __restrict__ Wd3, const float* __restrict__ bd3)
{
    __shared__ float sgend[NGRP*512];
    __shared__ float sPg[NGRP*Nst];
    __shared__ float sh[512];
    __shared__ float hrep[Nst], z1[HIDn], z2[HIDn], uu[Dd];
    __shared__ float sSxb[Dd], sSxxb;

    int b = blockIdx.x, off = threadIdx.x, n = off & 15;

    #pragma unroll
    for (int g = 0; g < NGRP; g++) {
        float lp[GL], ls[GL];
        #pragma unroll
        for (int j = 0; j < GL; j++) {
            int c = b*CPB + g*GL + j;
            lp[j] = g_P [c*Nst + n];
            ls[j] = g_sL[(size_t)c*512 + off];
        }
        float h = 0.f, pl = 1.f;
        #pragma unroll
        for (int j = 0; j < GL; j++) {
            int c = b*CPB + g*GL + j;
            g_hinL[(size_t)c*512 + off] = h;
            if (off < 16) g_Plp[((b*NGRP+g)*GL + j)*Nst + off] = pl;
            h  = fmaf(lp[j], h, ls[j]);
            pl *= lp[j];
        }
        sgend[g*512 + off] = h;
        if (off < 16) sPg[g*Nst + off] = pl;
    }
    __syncthreads();

    {
        float pg[NGRP], ge[NGRP];
        #pragma unroll
        for (int g = 0; g < NGRP; g++) {
            pg[g] = sPg[g*Nst + n];
            ge[g] = sgend[g*512 + off];
        }
        float h = 0.f;
        #pragma unroll
        for (int g = 0; g < NGRP; g++) {
            g_Hg[(size_t)(b*NGRP+g)*512 + off] = h;
            h = fmaf(pg[g], h, ge[g]);
        }
        sh[off] = h;
    }

    if (off < Dd) {
        float s = 0.f;
        #pragma unroll 8
        for (int k = 0; k < CPB; k++) s += g_SxP[(b*CPB + k)*Dd + off];
        sSxb[off] = s;
    } else if (off >= 32 && off < 64) {
        int l = off - 32;
        float s = g_SxxP[b*CPB + l] + g_SxxP[b*CPB + 32 + l];
        #pragma unroll
        for (int m = 16; m >= 1; m >>= 1) s += __shfl_xor_sync(0xffffffffu, s, m);
        if (l == 0) sSxxb = s;
    }
    __syncthreads();

    if (off < Nst) {
        float s = 0.f;
        #pragma unroll
        for (int d = 0; d < Dd; d++) s += sh[d*Nst + off];
        hrep[off] = s * (1.f/(float)Dd);
    }
    __syncthreads();
    if (off < HIDn) {
        float acc = bd1[off];
        #pragma unroll
        for (int nn = 0; nn < Nst; nn++) acc += hrep[nn] * Wd1[nn*HIDn + off];
        z1[off] = fmaxf(acc, 0.f);
    }
    __syncthreads();
    if (off < HIDn) {
        float acc = bd2[off];
        #pragma unroll 8
        for (int j = 0; j < HIDn; j++) acc += z1[j] * Wd2[j*HIDn + off];
        z2[off] = fmaxf(acc, 0.f);
    }
    __syncthreads();
    if (off < Dd) {
        float acc = bd3[off];
        #pragma unroll 8
        for (int j = 0; j < HIDn; j++) acc += z2[j] * Wd3[j*Dd + off];
        uu[off] = acc;
    }
    __syncthreads();
    if (off == 0) {
        float t1 = 0.f, t2 = 0.f;
        #pragma unroll
        for (int d = 0; d < Dd; d++) {
            t1 += uu[d]*uu[d];
            t2 += uu[d]*sSxb[d];
        }
        g_lossB[b] = (float)Ss * t1 - 2.f*t2 + sSxxb;
    }
}

// ---------------- K4: half-chunk blocks; y recombine + streaming expansion --
// grid = 1024 (2 blocks per chunk), block = 256; each block = 32 tokens.
__global__ __launch_bounds__(256) void k4(
    const float* __restrict__ Wout, const float* __restrict__ bout,
    float* __restrict__ out, long long out_size)
{
    __shared__ float shin[Dd*17];
    __shared__ float scpi[32*Nst];       // 512: this half's cpi
    __shared__ float sy[32*Dd];          // 1024
    __shared__ float4 sw[8], sb[8];

    int tid  = threadIdx.x;
    int ch   = blockIdx.x >> 1;
    int part = blockIdx.x & 1;
    int bg = ch >> 3, j = ch & 7;

    // compose h_in = hinL + Plp * Hg  (2 elements per thread)
    #pragma unroll
    for (int k = 0; k < 2; k++) {
        int i = tid + k*256;
        int d = i >> 4, n = i & 15;
        shin[d*17 + n] = fmaf(g_Plp[(bg*GL + j)*Nst + n],
                              g_Hg[(size_t)bg*512 + i],
                              g_hinL[(size_t)ch*512 + i]);
    }
    #pragma unroll
    for (int k = 0; k < 2; k++)
        scpi[tid + k*256] = g_cpi[(size_t)ch*1024 + part*512 + tid + k*256];
    if (tid < 8)       sw[tid]   = ((const float4*)Wout)[tid];
    else if (tid < 16) sb[tid-8] = ((const float4*)bout)[tid-8];
    __syncthreads();

    // y[t,d] = y_local + sum_n cpi[t,n] * h_in[d,n]   (this half's 32 tokens)
    #pragma unroll
    for (int k = 0; k < 4; k++) {
        int idx = tid + k*256;           // 0..1023
        int t = idx >> 5, d = idx & 31;
        float y = g_ylocA[(size_t)ch*2048 + part*1024 + idx];
        #pragma unroll
        for (int n = 0; n < Nst; n++)
            y = fmaf(scpi[t*Nst + n], shin[d*17 + n], y);
        sy[idx] = y;
    }
    __syncthreads();

    // streaming expansion: 32 tokens * 1024 floats = 8192 float4
    {
        int q = tid & 7, r0 = tid >> 3;  // r0 0..31
        float4 w4 = sw[q], b4 = sb[q];
        float4* o = (float4*)out + (size_t)ch*16384 + (size_t)part*8192;
        #pragma unroll
        for (int k = 0; k < 32; k++) {
            int r = r0 + k*32;           // 0..1023
            float y = sy[r];
            float4 v;
            v.x = fmaf(y, w4.x, b4.x);
            v.y = fmaf(y, w4.y, b4.y);
            v.z = fmaf(y, w4.z, b4.z);
            v.w = fmaf(y, w4.w, b4.w);
            __stcs(&o[r*8 + q], v);
        }
    }

    if (blockIdx.x == 0 && tid == 0 && out_size > (long long)OUT_ELEMS) {
        float s = 0.f;
        #pragma unroll
        for (int b = 0; b < Bb; b++) s += g_lossB[b];
        out[out_size - 1] = s * (1.f/(float)(Bb*Ss));
    }
}

// ---------------- launch -----------------------------------------------------
extern "C" void kernel_launch(void* const* d_in, const int* in_sizes, int n_in,
                              void* d_out, int out_size)
{
    const float* x    = (const float*)d_in[0];
    const float* A    = (const float*)d_in[1];
    const float* Win  = (const float*)d_in[2];
    const float* binp = (const float*)d_in[3];
    const float* Wdt  = (const float*)d_in[4];
    const float* bdt  = (const float*)d_in[5];
    const float* Wdtr = (const float*)d_in[6];
    const float* WB   = (const float*)d_in[7];
    const float* WC   = (const float*)d_in[8];
    const float* Wout = (const float*)d_in[9];
    const float* bout = (const float*)d_in[10];
    const float* Wd1  = (const float*)d_in[11];
    const float* bd1  = (const float*)d_in[12];
    const float* Wd2  = (const float*)d_in[13];
    const float* bd2  = (const float*)d_in[14];
    const float* Wd3  = (const float*)d_in[15];
    const float* bd3  = (const float*)d_in[16];
    float* out = (float*)d_out;

    kP<<<NCHUNK, 64>>>(x, A, Win, binp, Wdt, bdt, Wdtr, WB, WC);
    k3<<<Bb, 512>>>(Wd1, bd1, Wd2, bd2, Wd3, bd3);
    k4<<<NCHUNK*2, 256>>>(Wout, bout, out, (long long)out_size);
}

// round 16
// speedup vs baseline: 1.1785x; 1.0290x over previous
#include <cuda_runtime.h>
#include <math.h>

#define Bb   8
#define Ss   4096
#define Dd   32
#define Nst  16
#define HIDn 128
#define Ll   64
#define CPB  64
#define NCHUNK 512
#define NGRP 8
#define GL   8
#define TOK  32768
#define OUT_ELEMS ((size_t)TOK*Dd*Dd)

// ---------------- scratch ----------------------------------------------------
__device__ float g_P    [NCHUNK*Nst];
__device__ float g_sL   [NCHUNK*512];
__device__ float g_ylocA[TOK*Dd];     // y partial, n in [0,8)
__device__ float g_ylocB[TOK*Dd];     // y partial, n in [8,16)
__device__ float g_cpi  [TOK*Nst];
__device__ float g_hinL [NCHUNK*512];
__device__ float g_Hg   [Bb*NGRP*512];
__device__ float g_Plp  [Bb*NGRP*GL*Nst];
__device__ float g_SxP  [NCHUNK*Dd];
__device__ float g_SxxP [NCHUNK];
__device__ float g_lossB[Bb];

// ---------------- KP: fused projection + 2-warp split scan ------------------
// block = 64 threads = one chunk; grid = 512.
// Register-lean: B and C accumulated sequentially; scan y -> global partials.
__global__ __launch_bounds__(64) void kP(
    const float* __restrict__ x,   const float* __restrict__ A,
    const float* __restrict__ Win, const float* __restrict__ binp,
    const float* __restrict__ Wdt, const float* __restrict__ bdt,
    const float* __restrict__ Wdtr,
    const float* __restrict__ WB,  const float* __restrict__ WC)
{
    // staging (float4): [a 256 | bd 256 | c 256 | x 512]
    __shared__ __align__(16) float4 sstage[1280];        // 20 KB
    __shared__ __align__(16) float4 sWin4[Dd*8];         // 4 KB
    __shared__ __align__(16) float4 sWB4[Dd*4], sWC4[Dd*4];
    __shared__ __align__(16) float4 sbin4[8];
    __shared__ float sweff[Dd], sA[Nst];
    __shared__ float sSx2[2][Dd];
    __shared__ float sSxx2[2];
    __shared__ float sc0;

    int tid = threadIdx.x;
    int ch  = blockIdx.x;
    int token = ch*Ll + tid;

    for (int i = tid; i < Dd*8; i += 64) sWin4[i] = ((const float4*)Win)[i];
    for (int i = tid; i < Dd*4; i += 64) { sWB4[i] = ((const float4*)WB)[i];
                                           sWC4[i] = ((const float4*)WC)[i]; }
    if (tid < 8) sbin4[tid] = ((const float4*)binp)[tid];
    if (tid < Dd) {
        float s = 0.f;
        #pragma unroll
        for (int r = 0; r < Nst; r++) s += Wdt[tid*Nst + r] * Wdtr[r];
        sweff[tid] = s;
    }
    if (tid == 32) {
        float s = 0.f;
        #pragma unroll
        for (int r = 0; r < Nst; r++) s += bdt[r] * Wdtr[r];
        sc0 = s;
    }
    if (tid >= 40 && tid < 40 + Nst) sA[tid-40] = A[tid-40];
    __syncthreads();

    // ---- phase A: projection, one token per thread (register-lean) ----
    float xp[32];
    {
        float xr[32];
        const float4* xg = (const float4*)x + (size_t)token*8;
        #pragma unroll
        for (int j = 0; j < 8; j++) {
            float4 v = xg[j];
            xr[j*4+0] = v.x; xr[j*4+1] = v.y; xr[j*4+2] = v.z; xr[j*4+3] = v.w;
        }
        #pragma unroll
        for (int j = 0; j < 8; j++) {
            float4 b = sbin4[j];
            xp[j*4+0] = b.x; xp[j*4+1] = b.y; xp[j*4+2] = b.z; xp[j*4+3] = b.w;
        }
        #pragma unroll
        for (int k = 0; k < 32; k++) {
            float xk = xr[k];
            #pragma unroll
            for (int j = 0; j < 8; j++) {
                float4 w = sWin4[k*8+j];
                xp[j*4+0] = fmaf(xk, w.x, xp[j*4+0]);
                xp[j*4+1] = fmaf(xk, w.y, xp[j*4+1]);
                xp[j*4+2] = fmaf(xk, w.z, xp[j*4+2]);
                xp[j*4+3] = fmaf(xk, w.w, xp[j*4+3]);
            }
        }
    }

    float dt;
    {
        float zz = sc0;
        #pragma unroll
        for (int k = 0; k < 32; k++) zz = fmaf(xp[k], sweff[k], zz);
        dt = fmaxf(zz, 0.f) + log1pf(expf(-fabsf(zz)));
    }

    // ---- B projection -> stage a, bd (frees accumulators before C) ----
    {
        float bb[16];
        #pragma unroll
        for (int n = 0; n < 16; n++) bb[n] = 0.f;
        #pragma unroll
        for (int k = 0; k < 32; k++) {
            float xpk = xp[k];
            #pragma unroll
            for (int j = 0; j < 4; j++) {
                float4 wb = sWB4[k*4+j];
                bb[j*4+0] = fmaf(xpk, wb.x, bb[j*4+0]);
                bb[j*4+1] = fmaf(xpk, wb.y, bb[j*4+1]);
                bb[j*4+2] = fmaf(xpk, wb.z, bb[j*4+2]);
                bb[j*4+3] = fmaf(xpk, wb.w, bb[j*4+3]);
            }
        }
        #pragma unroll
        for (int j = 0; j < 4; j++) {
            sstage[      tid*4 + j] = make_float4(expf(dt*sA[j*4+0]), expf(dt*sA[j*4+1]),
                                                  expf(dt*sA[j*4+2]), expf(dt*sA[j*4+3]));
            sstage[256 + tid*4 + j] = make_float4(dt*bb[j*4+0], dt*bb[j*4+1],
                                                  dt*bb[j*4+2], dt*bb[j*4+3]);
        }
    }

    // ---- C projection -> stage c ----
    {
        float cc[16];
        #pragma unroll
        for (int n = 0; n < 16; n++) cc[n] = 0.f;
        #pragma unroll
        for (int k = 0; k < 32; k++) {
            float xpk = xp[k];
            #pragma unroll
            for (int j = 0; j < 4; j++) {
                float4 wc = sWC4[k*4+j];
                cc[j*4+0] = fmaf(xpk, wc.x, cc[j*4+0]);
                cc[j*4+1] = fmaf(xpk, wc.y, cc[j*4+1]);
                cc[j*4+2] = fmaf(xpk, wc.z, cc[j*4+2]);
                cc[j*4+3] = fmaf(xpk, wc.w, cc[j*4+3]);
            }
        }
        #pragma unroll
        for (int j = 0; j < 4; j++)
            sstage[512 + tid*4 + j] = make_float4(cc[j*4+0], cc[j*4+1], cc[j*4+2], cc[j*4+3]);
    }

    // ---- stage xp ----
    #pragma unroll
    for (int j = 0; j < 8; j++)
        sstage[768 + tid*8 + j] = make_float4(xp[j*4+0], xp[j*4+1], xp[j*4+2], xp[j*4+3]);

    int warp = tid >> 5, lane = tid & 31;

    // ---- x-stats, t-range split across warps ----
    {
        const float* xb = x + (size_t)ch*Ll*Dd + (size_t)warp*32*Dd;
        float s = 0.f, sq = 0.f;
        #pragma unroll 8
        for (int t = 0; t < 32; t++) {
            float v = xb[t*Dd + lane];
            s += v; sq = fmaf(v, v, sq);
        }
        sSx2[warp][lane] = s;
        #pragma unroll
        for (int m = 16; m >= 1; m >>= 1) sq += __shfl_xor_sync(0xffffffffu, sq, m);
        if (lane == 0) sSxx2[warp] = sq;
    }
    __syncthreads();

    // ---- scan: warp owns n in [8*warp, 8*warp+8); y -> global partial ----
    {
        const float4* s  = sstage;
        const float*  sa = (const float*)s;
        const float*  sc = (const float*)(s + 512);
        const float*  sx = (const float*)(s + 768);
        int np = warp*8 + (lane & 7);

        float h[8];
        #pragma unroll
        for (int n = 0; n < 8; n++) h[n] = 0.f;
        float pis = 1.f;

        float* yw   = (warp ? g_ylocB : g_ylocA) + (size_t)ch*Ll*Dd;
        float* cpio = g_cpi + (size_t)ch*Ll*Nst;

        #pragma unroll 2
        for (int t = 0; t < Ll; t++) {
            float av[8], bv[8], cv[8];
            *(float4*)&av[0] = s[t*4 + warp*2 + 0];       *(float4*)&av[4] = s[t*4 + warp*2 + 1];
            *(float4*)&bv[0] = s[256 + t*4 + warp*2 + 0]; *(float4*)&bv[4] = s[256 + t*4 + warp*2 + 1];
            *(float4*)&cv[0] = s[512 + t*4 + warp*2 + 0]; *(float4*)&cv[4] = s[512 + t*4 + warp*2 + 1];
            float xv = sx[t*32 + lane];

            float y0 = 0.f, y1 = 0.f;
            #pragma unroll
            for (int n = 0; n < 8; n += 2) {
                h[n+0] = fmaf(av[n+0], h[n+0], bv[n+0]*xv); y0 = fmaf(cv[n+0], h[n+0], y0);
                h[n+1] = fmaf(av[n+1], h[n+1], bv[n+1]*xv); y1 = fmaf(cv[n+1], h[n+1], y1);
            }
            yw[t*Dd + lane] = y0 + y1;

            pis *= sa[t*16 + np];
            if (lane < 8) cpio[t*Nst + np] = sc[t*16 + np] * pis;
        }

        float4* outL = (float4*)g_sL + (size_t)ch*128 + lane*4 + warp*2;
        outL[0] = make_float4(h[0],h[1],h[2],h[3]);
        outL[1] = make_float4(h[4],h[5],h[6],h[7]);
        if (lane < 8) g_P[ch*Nst + np] = pis;
    }

    if (tid < Dd)  g_SxP[ch*Dd + tid] = sSx2[0][tid] + sSx2[1][tid];
    if (tid == 32) g_SxxP[ch] = sSxx2[0] + sSxx2[1];
}

// ---------------- K3: per-batch combine + stat reduce + MLP loss ------------
__global__ __launch_bounds__(512) void k3(
    const float* __restrict__ Wd1, const float* __restrict__ bd1,
    const float* __restrict__ Wd2, const float* __restrict__ bd2,
    const float* __restrict__ Wd3, const float* __restrict__ bd3)
{
    __shared__ float sgend[NGRP*512];
    __shared__ float sPg[NGRP*Nst];
    __shared__ float sh[512];
    __shared__ float hrep[Nst], z1[HIDn], z2[HIDn], uu[Dd];
    __shared__ float sSxb[Dd], sSxxb;

    int b = blockIdx.x, off = threadIdx.x, n = off & 15;

    #pragma unroll
    for (int g = 0; g < NGRP; g++) {
        float lp[GL], ls[GL];
        #pragma unroll
        for (int j = 0; j < GL; j++) {
            int c = b*CPB + g*GL + j;
            lp[j] = g_P [c*Nst + n];
            ls[j] = g_sL[(size_t)c*512 + off];
        }
        float h = 0.f, pl = 1.f;
        #pragma unroll
        for (int j = 0; j < GL; j++) {
            int c = b*CPB + g*GL + j;
            g_hinL[(size_t)c*512 + off] = h;
            if (off < 16) g_Plp[((b*NGRP+g)*GL + j)*Nst + off] = pl;
            h  = fmaf(lp[j], h, ls[j]);
            pl *= lp[j];
        }
        sgend[g*512 + off] = h;
        if (off < 16) sPg[g*Nst + off] = pl;
    }
    __syncthreads();

    {
        float pg[NGRP], ge[NGRP];
        #pragma unroll
        for (int g = 0; g < NGRP; g++) {
            pg[g] = sPg[g*Nst + n];
            ge[g] = sgend[g*512 + off];
        }
        float h = 0.f;
        #pragma unroll
        for (int g = 0; g < NGRP; g++) {
            g_Hg[(size_t)(b*NGRP+g)*512 + off] = h;
            h = fmaf(pg[g], h, ge[g]);
        }
        sh[off] = h;
    }

    if (off < Dd) {
        float s = 0.f;
        #pragma unroll 8
        for (int k = 0; k < CPB; k++) s += g_SxP[(b*CPB + k)*Dd + off];
        sSxb[off] = s;
    } else if (off >= 32 && off < 64) {
        int l = off - 32;
        float s = g_SxxP[b*CPB + l] + g_SxxP[b*CPB + 32 + l];
        #pragma unroll
        for (int m = 16; m >= 1; m >>= 1) s += __shfl_xor_sync(0xffffffffu, s, m);
        if (l == 0) sSxxb = s;
    }
    __syncthreads();

    if (off < Nst) {
        float s = 0.f;
        #pragma unroll
        for (int d = 0; d < Dd; d++) s += sh[d*Nst + off];
        hrep[off] = s * (1.f/(float)Dd);
    }
    __syncthreads();
    if (off < HIDn) {
        float acc = bd1[off];
        #pragma unroll
        for (int nn = 0; nn < Nst; nn++) acc += hrep[nn] * Wd1[nn*HIDn + off];
        z1[off] = fmaxf(acc, 0.f);
    }
    __syncthreads();
    if (off < HIDn) {
        float acc = bd2[off];
        #pragma unroll 8
        for (int j = 0; j < HIDn; j++) acc += z1[j] * Wd2[j*HIDn + off];
        z2[off] = fmaxf(acc, 0.f);
    }
    __syncthreads();
    if (off < Dd) {
        float acc = bd3[off];
        #pragma unroll 8
        for (int j = 0; j < HIDn; j++) acc += z2[j] * Wd3[j*Dd + off];
        uu[off] = acc;
    }
    __syncthreads();
    if (off == 0) {
        float t1 = 0.f, t2 = 0.f;
        #pragma unroll
        for (int d = 0; d < Dd; d++) {
            t1 += uu[d]*uu[d];
            t2 += uu[d]*sSxb[d];
        }
        g_lossB[b] = (float)Ss * t1 - 2.f*t2 + sSxxb;
    }
}

// ---------------- K4: half-chunk blocks; y recombine + streaming expansion --
// grid = 1024 (2 blocks per chunk), block = 256; each block = 32 tokens.
__global__ __launch_bounds__(256) void k4(
    const float* __restrict__ Wout, const float* __restrict__ bout,
    float* __restrict__ out, long long out_size)
{
    __shared__ float shin[Dd*17];
    __shared__ float scpi[32*Nst];       // 512: this half's cpi
    __shared__ float sy[32*Dd];          // 1024
    __shared__ float4 sw[8], sb[8];

    int tid  = threadIdx.x;
    int ch   = blockIdx.x >> 1;
    int part = blockIdx.x & 1;
    int bg = ch >> 3, j = ch & 7;

    #pragma unroll
    for (int k = 0; k < 2; k++) {
        int i = tid + k*256;
        int d = i >> 4, n = i & 15;
        shin[d*17 + n] = fmaf(g_Plp[(bg*GL + j)*Nst + n],
                              g_Hg[(size_t)bg*512 + i],
                              g_hinL[(size_t)ch*512 + i]);
    }
    #pragma unroll
    for (int k = 0; k < 2; k++)
        scpi[tid + k*256] = g_cpi[(size_t)ch*1024 + part*512 + tid + k*256];
    if (tid < 8)       sw[tid]   = ((const float4*)Wout)[tid];
    else if (tid < 16) sb[tid-8] = ((const float4*)bout)[tid-8];
    __syncthreads();

    #pragma unroll
    for (int k = 0; k < 4; k++) {
        int idx = tid + k*256;           // 0..1023
        int t = idx >> 5, d = idx & 31;
        size_t gi = (size_t)ch*2048 + part*1024 + idx;
        float y = g_ylocA[gi] + g_ylocB[gi];
        #pragma unroll
        for (int n = 0; n < Nst; n++)
            y = fmaf(scpi[t*Nst + n], shin[d*17 + n], y);
        sy[idx] = y;
    }
    __syncthreads();

    {
        int q = tid & 7, r0 = tid >> 3;
        float4 w4 = sw[q], b4 = sb[q];
        float4* o = (float4*)out + (size_t)ch*16384 + (size_t)part*8192;
        #pragma unroll
        for (int k = 0; k < 32; k++) {
            int r = r0 + k*32;
            float y = sy[r];
            float4 v;
            v.x = fmaf(y, w4.x, b4.x);
            v.y = fmaf(y, w4.y, b4.y);
            v.z = fmaf(y, w4.z, b4.z);
            v.w = fmaf(y, w4.w, b4.w);
            __stcs(&o[r*8 + q], v);
        }
    }

    if (blockIdx.x == 0 && tid == 0 && out_size > (long long)OUT_ELEMS) {
        float s = 0.f;
        #pragma unroll
        for (int b = 0; b < Bb; b++) s += g_lossB[b];
        out[out_size - 1] = s * (1.f/(float)(Bb*Ss));
    }
}

// ---------------- launch -----------------------------------------------------
extern "C" void kernel_launch(void* const* d_in, const int* in_sizes, int n_in,
                              void* d_out, int out_size)
{
    const float* x    = (const float*)d_in[0];
    const float* A    = (const float*)d_in[1];
    const float* Win  = (const float*)d_in[2];
    const float* binp = (const float*)d_in[3];
    const float* Wdt  = (const float*)d_in[4];
    const float* bdt  = (const float*)d_in[5];
    const float* Wdtr = (const float*)d_in[6];
    const float* WB   = (const float*)d_in[7];
    const float* WC   = (const float*)d_in[8];
    const float* Wout = (const float*)d_in[9];
    const float* bout = (const float*)d_in[10];
    const float* Wd1  = (const float*)d_in[11];
    const float* bd1  = (const float*)d_in[12];
    const float* Wd2  = (const float*)d_in[13];
    const float* bd2  = (const float*)d_in[14];
    const float* Wd3  = (const float*)d_in[15];
    const float* bd3  = (const float*)d_in[16];
    float* out = (float*)d_out;

    kP<<<NCHUNK, 64>>>(x, A, Win, binp, Wdt, bdt, Wdtr, WB, WC);
    k3<<<Bb, 512>>>(Wd1, bd1, Wd2, bd2, Wd3, bd3);
    k4<<<NCHUNK*2, 256>>>(Wout, bout, out, (long long)out_size);
}

// round 17
// speedup vs baseline: 1.1791x; 1.0006x over previous
#include <cuda_runtime.h>
#include <math.h>

#define Bb   8
#define Ss   4096
#define Dd   32
#define Nst  16
#define HIDn 128
#define Ll   64
#define CPB  64
#define NCHUNK 512
#define NGRP 8
#define GL   8
#define TOK  32768
#define OUT_ELEMS ((size_t)TOK*Dd*Dd)

typedef unsigned long long ull;

// ---- packed f32x2 helpers (Blackwell) ----
__device__ __forceinline__ ull pk2(float a, float b) {
    ull r; asm("mov.b64 %0,{%1,%2};" : "=l"(r) : "f"(a), "f"(b)); return r;
}
__device__ __forceinline__ void upk2(ull v, float& a, float& b) {
    asm("mov.b64 {%0,%1},%2;" : "=f"(a), "=f"(b) : "l"(v));
}
__device__ __forceinline__ ull f2fma(ull a, ull b, ull c) {
    ull d; asm("fma.rn.f32x2 %0,%1,%2,%3;" : "=l"(d) : "l"(a), "l"(b), "l"(c)); return d;
}
__device__ __forceinline__ ull f2mul(ull a, ull b) {
    ull d; asm("mul.rn.f32x2 %0,%1,%2;" : "=l"(d) : "l"(a), "l"(b)); return d;
}
__device__ __forceinline__ ull d2l(double v) { return __double_as_longlong(v); }

// ---------------- scratch ----------------------------------------------------
__device__ float g_P    [NCHUNK*Nst];
__device__ float g_sL   [NCHUNK*512];
__device__ float g_ylocA[TOK*Dd];     // y partial, n in [0,8)
__device__ float g_ylocB[TOK*Dd];     // y partial, n in [8,16)
__device__ float g_cpi  [TOK*Nst];
__device__ float g_hinL [NCHUNK*512];
__device__ float g_Hg   [Bb*NGRP*512];
__device__ float g_Plp  [Bb*NGRP*GL*Nst];
__device__ float g_SxP  [NCHUNK*Dd];
__device__ float g_SxxP [NCHUNK];
__device__ float g_lossB[Bb];

// ---------------- KP: fused projection (f32x2) + 2-warp split scan ----------
// block = 64 threads = one chunk; grid = 512.
__global__ __launch_bounds__(64) void kP(
    const float* __restrict__ x,   const float* __restrict__ A,
    const float* __restrict__ Win, const float* __restrict__ binp,
    const float* __restrict__ Wdt, const float* __restrict__ bdt,
    const float* __restrict__ Wdtr,
    const float* __restrict__ WB,  const float* __restrict__ WC)
{
    // staging (float4): [a 256 | bd 256 | c 256 | x 512]
    __shared__ __align__(16) float4 sstage[1280];        // 20 KB
    __shared__ __align__(16) float4 sWin4[Dd*8];         // 4 KB
    __shared__ __align__(16) float4 sWB4[Dd*4], sWC4[Dd*4];
    __shared__ __align__(16) float4 sbin4[8];
    __shared__ float sweff[Dd], sA[Nst];
    __shared__ float sSx2[2][Dd];
    __shared__ float sSxx2[2];
    __shared__ float sc0;

    int tid = threadIdx.x;
    int ch  = blockIdx.x;
    int token = ch*Ll + tid;

    for (int i = tid; i < Dd*8; i += 64) sWin4[i] = ((const float4*)Win)[i];
    for (int i = tid; i < Dd*4; i += 64) { sWB4[i] = ((const float4*)WB)[i];
                                           sWC4[i] = ((const float4*)WC)[i]; }
    if (tid < 8) sbin4[tid] = ((const float4*)binp)[tid];
    if (tid < Dd) {
        float s = 0.f;
        #pragma unroll
        for (int r = 0; r < Nst; r++) s += Wdt[tid*Nst + r] * Wdtr[r];
        sweff[tid] = s;
    }
    if (tid == 32) {
        float s = 0.f;
        #pragma unroll
        for (int r = 0; r < Nst; r++) s += bdt[r] * Wdtr[r];
        sc0 = s;
    }
    if (tid >= 40 && tid < 40 + Nst) sA[tid-40] = A[tid-40];
    __syncthreads();

    // ---- phase A: xp = x@Win + bin  (packed f32x2 FMAs) ----
    ull xp2[16];
    {
        float xr[32];
        const float4* xg = (const float4*)x + (size_t)token*8;
        #pragma unroll
        for (int j = 0; j < 8; j++) {
            float4 v = xg[j];
            xr[j*4+0] = v.x; xr[j*4+1] = v.y; xr[j*4+2] = v.z; xr[j*4+3] = v.w;
        }
        const double2* bin2 = (const double2*)sbin4;
        #pragma unroll
        for (int j = 0; j < 8; j++) {
            double2 b = bin2[j];
            xp2[2*j]   = d2l(b.x);
            xp2[2*j+1] = d2l(b.y);
        }
        const double2* Win2 = (const double2*)sWin4;
        #pragma unroll
        for (int k = 0; k < 32; k++) {
            ull xk2 = pk2(xr[k], xr[k]);
            #pragma unroll
            for (int j = 0; j < 8; j++) {
                double2 w = Win2[k*8 + j];
                xp2[2*j]   = f2fma(xk2, d2l(w.x), xp2[2*j]);
                xp2[2*j+1] = f2fma(xk2, d2l(w.y), xp2[2*j+1]);
            }
        }
    }

    // stage xp (bit-identical pair layout)
    {
        double2* xo = (double2*)&sstage[768 + tid*8];
        #pragma unroll
        for (int j = 0; j < 8; j++)
            xo[j] = make_double2(__longlong_as_double(xp2[2*j]),
                                 __longlong_as_double(xp2[2*j+1]));
    }

    // unpack xp for dt + B/C multiplier use
    float xpf[32];
    #pragma unroll
    for (int j = 0; j < 16; j++) upk2(xp2[j], xpf[2*j], xpf[2*j+1]);

    float dt;
    {
        float zz = sc0;
        #pragma unroll
        for (int k = 0; k < 32; k++) zz = fmaf(xpf[k], sweff[k], zz);
        dt = fmaxf(zz, 0.f) + log1pf(expf(-fabsf(zz)));
    }

    // ---- B and C projections, merged, packed ----
    {
        ull bb2[8], cc2[8];
        ull z = pk2(0.f, 0.f);
        #pragma unroll
        for (int j = 0; j < 8; j++) { bb2[j] = z; cc2[j] = z; }
        const double2* WB2 = (const double2*)sWB4;
        const double2* WC2 = (const double2*)sWC4;
        #pragma unroll
        for (int k = 0; k < 32; k++) {
            ull xk2 = pk2(xpf[k], xpf[k]);
            #pragma unroll
            for (int j = 0; j < 4; j++) {
                double2 wb = WB2[k*4 + j];
                double2 wc = WC2[k*4 + j];
                bb2[2*j]   = f2fma(xk2, d2l(wb.x), bb2[2*j]);
                bb2[2*j+1] = f2fma(xk2, d2l(wb.y), bb2[2*j+1]);
                cc2[2*j]   = f2fma(xk2, d2l(wc.x), cc2[2*j]);
                cc2[2*j+1] = f2fma(xk2, d2l(wc.y), cc2[2*j+1]);
            }
        }

        // stage a (scalar exps), bd = dt*bb (packed), c (direct)
        ull dt2 = pk2(dt, dt);
        #pragma unroll
        for (int j = 0; j < 4; j++) {
            sstage[tid*4 + j] = make_float4(expf(dt*sA[j*4+0]), expf(dt*sA[j*4+1]),
                                            expf(dt*sA[j*4+2]), expf(dt*sA[j*4+3]));
            *(double2*)&sstage[256 + tid*4 + j] =
                make_double2(__longlong_as_double(f2mul(dt2, bb2[2*j])),
                             __longlong_as_double(f2mul(dt2, bb2[2*j+1])));
            *(double2*)&sstage[512 + tid*4 + j] =
                make_double2(__longlong_as_double(cc2[2*j]),
                             __longlong_as_double(cc2[2*j+1]));
        }
    }

    int warp = tid >> 5, lane = tid & 31;

    // ---- x-stats, t-range split across warps ----
    {
        const float* xb = x + (size_t)ch*Ll*Dd + (size_t)warp*32*Dd;
        float s = 0.f, sq = 0.f;
        #pragma unroll 8
        for (int t = 0; t < 32; t++) {
            float v = xb[t*Dd + lane];
            s += v; sq = fmaf(v, v, sq);
        }
        sSx2[warp][lane] = s;
        #pragma unroll
        for (int m = 16; m >= 1; m >>= 1) sq += __shfl_xor_sync(0xffffffffu, sq, m);
        if (lane == 0) sSxx2[warp] = sq;
    }
    __syncthreads();

    // ---- scan: warp owns n in [8*warp, 8*warp+8); y -> global partial ----
    {
        const float4* s  = sstage;
        const float*  sa = (const float*)s;
        const float*  sc = (const float*)(s + 512);
        const float*  sx = (const float*)(s + 768);
        int np = warp*8 + (lane & 7);

        float h[8];
        #pragma unroll
        for (int n = 0; n < 8; n++) h[n] = 0.f;
        float pis = 1.f;

        float* yw   = (warp ? g_ylocB : g_ylocA) + (size_t)ch*Ll*Dd;
        float* cpio = g_cpi + (size_t)ch*Ll*Nst;

        #pragma unroll 2
        for (int t = 0; t < Ll; t++) {
            float av[8], bv[8], cv[8];
            *(float4*)&av[0] = s[t*4 + warp*2 + 0];       *(float4*)&av[4] = s[t*4 + warp*2 + 1];
            *(float4*)&bv[0] = s[256 + t*4 + warp*2 + 0]; *(float4*)&bv[4] = s[256 + t*4 + warp*2 + 1];
            *(float4*)&cv[0] = s[512 + t*4 + warp*2 + 0]; *(float4*)&cv[4] = s[512 + t*4 + warp*2 + 1];
            float xv = sx[t*32 + lane];

            float y0 = 0.f, y1 = 0.f;
            #pragma unroll
            for (int n = 0; n < 8; n += 2) {
                h[n+0] = fmaf(av[n+0], h[n+0], bv[n+0]*xv); y0 = fmaf(cv[n+0], h[n+0], y0);
                h[n+1] = fmaf(av[n+1], h[n+1], bv[n+1]*xv); y1 = fmaf(cv[n+1], h[n+1], y1);
            }
            yw[t*Dd + lane] = y0 + y1;

            pis *= sa[t*16 + np];
            if (lane < 8) cpio[t*Nst + np] = sc[t*16 + np] * pis;
        }

        float4* outL = (float4*)g_sL + (size_t)ch*128 + lane*4 + warp*2;
        outL[0] = make_float4(h[0],h[1],h[2],h[3]);
        outL[1] = make_float4(h[4],h[5],h[6],h[7]);
        if (lane < 8) g_P[ch*Nst + np] = pis;
    }

    if (tid < Dd)  g_SxP[ch*Dd + tid] = sSx2[0][tid] + sSx2[1][tid];
    if (tid == 32) g_SxxP[ch] = sSxx2[0] + sSxx2[1];
}

// ---------------- K3: per-batch combine + stat reduce + MLP loss ------------
__global__ __launch_bounds__(512) void k3(
    const float* __restrict__ Wd1, const float* __restrict__ bd1,
    const float* __restrict__ Wd2, const float* __restrict__ bd2,
    const float* __restrict__ Wd3, const float* __restrict__ bd3)
{
    __shared__ float sgend[NGRP*512];
    __shared__ float sPg[NGRP*Nst];
    __shared__ float sh[512];
    __shared__ float hrep[Nst], z1[HIDn], z2[HIDn], uu[Dd];
    __shared__ float sSxb[Dd], sSxxb;

    int b = blockIdx.x, off = threadIdx.x, n = off & 15;

    #pragma unroll
    for (int g = 0; g < NGRP; g++) {
        float lp[GL], ls[GL];
        #pragma unroll
        for (int j = 0; j < GL; j++) {
            int c = b*CPB + g*GL + j;
            lp[j] = g_P [c*Nst + n];
            ls[j] = g_sL[(size_t)c*512 + off];
        }
        float h = 0.f, pl = 1.f;
        #pragma unroll
        for (int j = 0; j < GL; j++) {
            int c = b*CPB + g*GL + j;
            g_hinL[(size_t)c*512 + off] = h;
            if (off < 16) g_Plp[((b*NGRP+g)*GL + j)*Nst + off] = pl;
            h  = fmaf(lp[j], h, ls[j]);
            pl *= lp[j];
        }
        sgend[g*512 + off] = h;
        if (off < 16) sPg[g*Nst + off] = pl;
    }
    __syncthreads();

    {
        float pg[NGRP], ge[NGRP];
        #pragma unroll
        for (int g = 0; g < NGRP; g++) {
            pg[g] = sPg[g*Nst + n];
            ge[g] = sgend[g*512 + off];
        }
        float h = 0.f;
        #pragma unroll
        for (int g = 0; g < NGRP; g++) {
            g_Hg[(size_t)(b*NGRP+g)*512 + off] = h;
            h = fmaf(pg[g], h, ge[g]);
        }
        sh[off] = h;
    }

    if (off < Dd) {
        float s = 0.f;
        #pragma unroll 8
        for (int k = 0; k < CPB; k++) s += g_SxP[(b*CPB + k)*Dd + off];
        sSxb[off] = s;
    } else if (off >= 32 && off < 64) {
        int l = off - 32;
        float s = g_SxxP[b*CPB + l] + g_SxxP[b*CPB + 32 + l];
        #pragma unroll
        for (int m = 16; m >= 1; m >>= 1) s += __shfl_xor_sync(0xffffffffu, s, m);
        if (l == 0) sSxxb = s;
    }
    __syncthreads();

    if (off < Nst) {
        float s = 0.f;
        #pragma unroll
        for (int d = 0; d < Dd; d++) s += sh[d*Nst + off];
        hrep[off] = s * (1.f/(float)Dd);
    }
    __syncthreads();
    if (off < HIDn) {
        float acc = bd1[off];
        #pragma unroll
        for (int nn = 0; nn < Nst; nn++) acc += hrep[nn] * Wd1[nn*HIDn + off];
        z1[off] = fmaxf(acc, 0.f);
    }
    __syncthreads();
    if (off < HIDn) {
        float acc = bd2[off];
        #pragma unroll 8
        for (int j = 0; j < HIDn; j++) acc += z1[j] * Wd2[j*HIDn + off];
        z2[off] = fmaxf(acc, 0.f);
    }
    __syncthreads();
    if (off < Dd) {
        float acc = bd3[off];
        #pragma unroll 8
        for (int j = 0; j < HIDn; j++) acc += z2[j] * Wd3[j*Dd + off];
        uu[off] = acc;
    }
    __syncthreads();
    if (off == 0) {
        float t1 = 0.f, t2 = 0.f;
        #pragma unroll
        for (int d = 0; d < Dd; d++) {
            t1 += uu[d]*uu[d];
            t2 += uu[d]*sSxb[d];
        }
        g_lossB[b] = (float)Ss * t1 - 2.f*t2 + sSxxb;
    }
}

// ---------------- K4: half-chunk blocks; y recombine + streaming expansion --
// grid = 1024 (2 blocks per chunk), block = 256; each block = 32 tokens.
__global__ __launch_bounds__(256) void k4(
    const float* __restrict__ Wout, const float* __restrict__ bout,
    float* __restrict__ out, long long out_size)
{
    __shared__ float shin[Dd*17];
    __shared__ float scpi[32*Nst];       // 512: this half's cpi
    __shared__ float sy[32*Dd];          // 1024
    __shared__ float4 sw[8], sb[8];

    int tid  = threadIdx.x;
    int ch   = blockIdx.x >> 1;
    int part = blockIdx.x & 1;
    int bg = ch >> 3, j = ch & 7;

    #pragma unroll
    for (int k = 0; k < 2; k++) {
        int i = tid + k*256;
        int d = i >> 4, n = i & 15;
        shin[d*17 + n] = fmaf(g_Plp[(bg*GL + j)*Nst + n],
                              g_Hg[(size_t)bg*512 + i],
                              g_hinL[(size_t)ch*512 + i]);
    }
    #pragma unroll
    for (int k = 0; k < 2; k++)
        scpi[tid + k*256] = g_cpi[(size_t)ch*1024 + part*512 + tid + k*256];
    if (tid < 8)       sw[tid]   = ((const float4*)Wout)[tid];
    else if (tid < 16) sb[tid-8] = ((const float4*)bout)[tid-8];
    __syncthreads();

    #pragma unroll
    for (int k = 0; k < 4; k++) {
        int idx = tid + k*256;           // 0..1023
        int t = idx >> 5, d = idx & 31;
        size_t gi = (size_t)ch*2048 + part*1024 + idx;
        float y = g_ylocA[gi] + g_ylocB[gi];
        #pragma unroll
        for (int n = 0; n < Nst; n++)
            y = fmaf(scpi[t*Nst + n], shin[d*17 + n], y);
        sy[idx] = y;
    }
    __syncthreads();

    {
        int q = tid & 7, r0 = tid >> 3;
        float4 w4 = sw[q], b4 = sb[q];
        float4* o = (float4*)out + (size_t)ch*16384 + (size_t)part*8192;
        #pragma unroll
        for (int k = 0; k < 32; k++) {
            int r = r0 + k*32;
            float y = sy[r];
            float4 v;
            v.x = fmaf(y, w4.x, b4.x);
            v.y = fmaf(y, w4.y, b4.y);
            v.z = fmaf(y, w4.z, b4.z);
            v.w = fmaf(y, w4.w, b4.w);
            __stcs(&o[r*8 + q], v);
        }
    }

    if (blockIdx.x == 0 && tid == 0 && out_size > (long long)OUT_ELEMS) {
        float s = 0.f;
        #pragma unroll
        for (int b = 0; b < Bb; b++) s += g_lossB[b];
        out[out_size - 1] = s * (1.f/(float)(Bb*Ss));
    }
}

// ---------------- launch -----------------------------------------------------
extern "C" void kernel_launch(void* const* d_in, const int* in_sizes, int n_in,
                              void* d_out, int out_size)
{
    const float* x    = (const float*)d_in[0];
    const float* A    = (const float*)d_in[1];
    const float* Win  = (const float*)d_in[2];
    const float* binp = (const float*)d_in[3];
    const float* Wdt  = (const float*)d_in[4];
    const float* bdt  = (const float*)d_in[5];
    const float* Wdtr = (const float*)d_in[6];
    const float* WB   = (const float*)d_in[7];
    const float* WC   = (const float*)d_in[8];
    const float* Wout = (const float*)d_in[9];
    const float* bout = (const float*)d_in[10];
    const float* Wd1  = (const float*)d_in[11];
    const float* bd1  = (const float*)d_in[12];
    const float* Wd2  = (const float*)d_in[13];
    const float* bd2  = (const float*)d_in[14];
    const float* Wd3  = (const float*)d_in[15];
    const float* bd3  = (const float*)d_in[16];
    float* out = (float*)d_out;

    kP<<<NCHUNK, 64>>>(x, A, Win, binp, Wdt, bdt, Wdtr, WB, WC);
    k3<<<Bb, 512>>>(Wd1, bd1, Wd2, bd2, Wd3, bd3);
    k4<<<NCHUNK*2, 256>>>(Wout, bout, out, (long long)out_size);
}